// round 4
// baseline (speedup 1.0000x reference)
#include <cuda_runtime.h>
#include <cstddef>

#define NPTS 1024
#define BATCH 32
#define MTOT 32768
#define EPS_BN 1e-5f

// ---------------- static scratch (no allocations allowed) ----------------
__device__ float g_z1[(size_t)MTOT * 64];
__device__ float g_z2[(size_t)MTOT * 64];
__device__ float g_z3[(size_t)MTOT * 64];
__device__ float g_z4[(size_t)MTOT * 128];
__device__ float g_z5[(size_t)MTOT * 1024];
__device__ float g_z6[(size_t)MTOT * 512];
__device__ float g_z7[(size_t)MTOT * 256];
__device__ float g_z8[(size_t)MTOT * 128];
__device__ float g_z9[(size_t)MTOT * 128];

// per-channel stats, packed by layer offset:
// L1:0(64) L2:64 L3:128 L4:192(128) L5:320(1024) L6:1344(512) L7:1856(256) L8:2112(128) L9:2240(128) -> 2368
__device__ float g_sum[2368];
__device__ float g_sq[2368];
__device__ float g_mean[2368];
__device__ float g_rstd[2368];

__device__ unsigned g_max5[BATCH * 1024];   // order-monotone uint-mapped float max
__device__ float g_const6[BATCH * 512];     // per-batch gf contribution to layer 6

// ---------------- helpers ----------------
__device__ __forceinline__ float fast_tanh(float x) {
    // tanh(x) = 1 - 2/(exp(2x)+1); ex2.approx + rcp.approx, rel err ~1e-6
    float e, r;
    asm("ex2.approx.f32 %0, %1;" : "=f"(e) : "f"(x * 2.8853900817779268f)); // 2*log2(e)
    asm("rcp.approx.f32 %0, %1;" : "=f"(r) : "f"(e + 1.0f));
    return 1.0f - 2.0f * r;
}

// Jacobi polys, degree 3, a=b=1 (exact constants from the reference recurrence)
__device__ __forceinline__ void jacobi4(float t, float& p0, float& p1, float& p2, float& p3) {
    p0 = 1.0f;
    p1 = 2.0f * t;
    p2 = 1.875f * t * p1 - 0.75f;
    p3 = 1.8666666666666667f * t * p2 - 0.8f * p1;
}

__device__ __forceinline__ unsigned fmap(float f) {
    unsigned u = __float_as_uint(f);
    return (u & 0x80000000u) ? ~u : (u | 0x80000000u);
}
__device__ __forceinline__ float funmap(unsigned u) {
    return (u & 0x80000000u) ? __uint_as_float(u & 0x7fffffffu) : __uint_as_float(~u);
}

// ---------------- kernels ----------------
__global__ void zero_kernel() {
    int i = blockIdx.x * 256 + threadIdx.x;
    if (i < 2368) { g_sum[i] = 0.f; g_sq[i] = 0.f; }
    if (i < BATCH * 1024) g_max5[i] = 0u;  // 0 < fmap(any finite float)
}

__global__ void finalize_kernel(const float* __restrict__ s, const float* __restrict__ q,
                                float* __restrict__ mean, float* __restrict__ rstd, int C) {
    int i = blockIdx.x * 64 + threadIdx.x;
    if (i < C) {
        float m = s[i] * (1.0f / 32768.0f);
        float v = q[i] * (1.0f / 32768.0f) - m * m;
        mean[i] = m;
        rstd[i] = rsqrtf(v + EPS_BN);
    }
}

// max over n of z5 per (b, c); grid (32, 8) x 256 threads; 4 channels/thread
__global__ void maxpool5_kernel() {
    int b = blockIdx.x;
    int n0 = blockIdx.y * 128;
    int t = threadIdx.x;
    float mx[4];
#pragma unroll
    for (int j = 0; j < 4; j++) mx[j] = -3.4e38f;
    for (int n = n0; n < n0 + 128; n++) {
        const float* row = &g_z5[(size_t)(b * 1024 + n) * 1024];
#pragma unroll
        for (int j = 0; j < 4; j++) mx[j] = fmaxf(mx[j], row[t + j * 256]);
    }
#pragma unroll
    for (int j = 0; j < 4; j++)
        atomicMax(&g_max5[b * 1024 + t + j * 256], fmap(mx[j]));
}

// const6[b][o] = sum_{i in [0,1024)} phi(tanh(BN5(max5[b][i]))) . w6[64+i][o][:]
// grid (8, 32), 64 threads
__global__ void const6_kernel(const float* __restrict__ w6) {
    __shared__ float sb[1024][4];
    int b = blockIdx.y;
    int o = blockIdx.x * 64 + threadIdx.x;
    const float* mean5 = &g_mean[320];
    const float* rstd5 = &g_rstd[320];
    for (int i = threadIdx.x; i < 1024; i += 64) {
        float f = funmap(g_max5[b * 1024 + i]);
        float t = fast_tanh((f - mean5[i]) * rstd5[i]);
        float p0, p1, p2, p3;
        jacobi4(t, p0, p1, p2, p3);
        sb[i][0] = p0; sb[i][1] = p1; sb[i][2] = p2; sb[i][3] = p3;
    }
    __syncthreads();
    float acc = 0.f;
    for (int i = 0; i < 1024; i++) {
        float4 wv = *reinterpret_cast<const float4*>(&w6[((size_t)(64 + i) * 512 + o) * 4]);
        acc += sb[i][0] * wv.x + sb[i][1] * wv.y + sb[i][2] * wv.z + sb[i][3] * wv.w;
    }
    g_const6[b * 512 + o] = acc;
}

// Fused KAN layer GEMM:
//   out[m, o] = sum_{i,d} P_d(tanh((in[m,i]-mean[i])*rstd[i])) * w[i, o, d]  (+ const6[b,o] if HASCONST)
// plus per-channel sum/sumsq accumulation (unless LAST).
// FIRST: input is x with layout (B, C_in, N), no BN on input.
// LAST:  output layout (B, C_out, N), no stats.
template <bool FIRST, bool LAST, bool HASCONST>
__global__ __launch_bounds__(256) void kan_gemm(
    const float* __restrict__ in, const float* __restrict__ w,
    const float* __restrict__ mean, const float* __restrict__ rstd,
    float* __restrict__ out, float* __restrict__ ssum, float* __restrict__ ssq,
    const float* __restrict__ cst, int C_in, int C_out)
{
    __shared__ float As[32][128];   // [k = ch*4+d][row]
    __shared__ float Bs[32][64];    // [k][o]
    __shared__ float redS[16][64];
    __shared__ float redQ[16][64];

    const int tid = threadIdx.x;
    const int tcol = tid & 15, trow = tid >> 4;
    const int m0 = blockIdx.y * 128;
    const int n0 = blockIdx.x * 64;

    float acc[8][4];
    if (HASCONST) {
        const int b = m0 >> 10;   // 128-row tiles never cross batch (1024 % 128 == 0)
#pragma unroll
        for (int c = 0; c < 4; c++) {
            float v = cst[b * C_out + n0 + tcol * 4 + c];
#pragma unroll
            for (int r = 0; r < 8; r++) acc[r][c] = v;
        }
    } else {
#pragma unroll
        for (int r = 0; r < 8; r++)
#pragma unroll
            for (int c = 0; c < 4; c++) acc[r][c] = 0.f;
    }

    const int numKT = (C_in + 7) >> 3;
    for (int kt = 0; kt < numKT; kt++) {
        const int ch0 = kt * 8;

        // ---- A tile: 128 rows x 8 channels -> basis expand ----
        if (FIRST) {
            const int ch = tid & 7;
            const int rb = tid >> 3;
#pragma unroll
            for (int p = 0; p < 4; p++) {
                int row = rb + p * 32;
                float p0 = 0.f, p1 = 0.f, p2 = 0.f, p3 = 0.f;
                if (ch0 + ch < C_in) {
                    int m = m0 + row;
                    float v = in[(m >> 10) * (2 * NPTS) + (ch0 + ch) * NPTS + (m & (NPTS - 1))];
                    float t = fast_tanh(v);
                    jacobi4(t, p0, p1, p2, p3);
                }
                int k = ch * 4;
                As[k + 0][row] = p0; As[k + 1][row] = p1;
                As[k + 2][row] = p2; As[k + 3][row] = p3;
            }
        } else {
            // C_in is a multiple of 8 for all non-first layers
            const int row = tid >> 1;
            const int chq = (tid & 1) * 4;
            const float4 v4 =
                *reinterpret_cast<const float4*>(&in[(size_t)(m0 + row) * C_in + ch0 + chq]);
            const float vv[4] = {v4.x, v4.y, v4.z, v4.w};
#pragma unroll
            for (int j = 0; j < 4; j++) {
                int cc = ch0 + chq + j;
                float t = fast_tanh((vv[j] - mean[cc]) * rstd[cc]);
                float p0, p1, p2, p3;
                jacobi4(t, p0, p1, p2, p3);
                int k = (chq + j) * 4;
                As[k + 0][row] = p0; As[k + 1][row] = p1;
                As[k + 2][row] = p2; As[k + 3][row] = p3;
            }
        }

        // ---- B tile: w[(ch0+ch), n0+o, 0..3] as float4 ----
#pragma unroll
        for (int p = 0; p < 2; p++) {
            int f = tid + p * 256;      // float4 index 0..511
            int ch = f >> 6;
            int o = f & 63;
            int cc = ch0 + ch;
            int col = n0 + o;
            float4 wv = make_float4(0.f, 0.f, 0.f, 0.f);
            if (cc < C_in && col < C_out)
                wv = *reinterpret_cast<const float4*>(&w[((size_t)cc * C_out + col) * 4]);
            int k = ch * 4;
            Bs[k + 0][o] = wv.x; Bs[k + 1][o] = wv.y;
            Bs[k + 2][o] = wv.z; Bs[k + 3][o] = wv.w;
        }
        __syncthreads();

#pragma unroll
        for (int k = 0; k < 32; k++) {
            float a[8], b[4];
#pragma unroll
            for (int r = 0; r < 8; r++) a[r] = As[k][trow * 8 + r];
#pragma unroll
            for (int c = 0; c < 4; c++) b[c] = Bs[k][tcol * 4 + c];
#pragma unroll
            for (int r = 0; r < 8; r++)
#pragma unroll
                for (int c = 0; c < 4; c++) acc[r][c] = fmaf(a[r], b[c], acc[r][c]);
        }
        __syncthreads();
    }

    if (LAST) {
#pragma unroll
        for (int r = 0; r < 8; r++) {
            int m = m0 + trow * 8 + r;
            int b = m >> 10, n = m & (NPTS - 1);
#pragma unroll
            for (int c = 0; c < 4; c++) {
                int col = n0 + tcol * 4 + c;
                if (col < C_out) out[((size_t)b * C_out + col) * NPTS + n] = acc[r][c];
            }
        }
    } else {
#pragma unroll
        for (int r = 0; r < 8; r++) {
            size_t m = m0 + trow * 8 + r;
            float4 v = make_float4(acc[r][0], acc[r][1], acc[r][2], acc[r][3]);
            *reinterpret_cast<float4*>(&out[m * C_out + n0 + tcol * 4]) = v;
        }
        float s[4] = {0, 0, 0, 0}, q[4] = {0, 0, 0, 0};
#pragma unroll
        for (int r = 0; r < 8; r++)
#pragma unroll
            for (int c = 0; c < 4; c++) {
                s[c] += acc[r][c];
                q[c] += acc[r][c] * acc[r][c];
            }
#pragma unroll
        for (int c = 0; c < 4; c++) {
            redS[trow][tcol * 4 + c] = s[c];
            redQ[trow][tcol * 4 + c] = q[c];
        }
        __syncthreads();
        if (tid < 64 && (n0 + tid) < C_out) {
            float ts = 0.f, tq = 0.f;
#pragma unroll
            for (int r = 0; r < 16; r++) { ts += redS[r][tid]; tq += redQ[r][tid]; }
            atomicAdd(&ssum[n0 + tid], ts);
            atomicAdd(&ssq[n0 + tid], tq);
        }
    }
}

// ---------------- launch ----------------
static inline int cdiv(int a, int b) { return (a + b - 1) / b; }

extern "C" void kernel_launch(void* const* d_in, const int* in_sizes, int n_in,
                              void* d_out, int out_size) {
    (void)in_sizes; (void)n_in; (void)out_size;
    const float* x   = (const float*)d_in[0];
    const float* w1  = (const float*)d_in[1];
    const float* w2  = (const float*)d_in[2];
    const float* w3  = (const float*)d_in[3];
    const float* w4  = (const float*)d_in[4];
    const float* w5  = (const float*)d_in[5];
    const float* w6  = (const float*)d_in[6];
    const float* w7  = (const float*)d_in[7];
    const float* w8  = (const float*)d_in[8];
    const float* w9  = (const float*)d_in[9];
    const float* w10 = (const float*)d_in[10];
    float* outp = (float*)d_out;

    float *z1, *z2, *z3, *z4, *z5, *z6, *z7, *z8, *z9;
    float *sum, *sq, *mean, *rstd, *cst6;
    cudaGetSymbolAddress((void**)&z1, g_z1);
    cudaGetSymbolAddress((void**)&z2, g_z2);
    cudaGetSymbolAddress((void**)&z3, g_z3);
    cudaGetSymbolAddress((void**)&z4, g_z4);
    cudaGetSymbolAddress((void**)&z5, g_z5);
    cudaGetSymbolAddress((void**)&z6, g_z6);
    cudaGetSymbolAddress((void**)&z7, g_z7);
    cudaGetSymbolAddress((void**)&z8, g_z8);
    cudaGetSymbolAddress((void**)&z9, g_z9);
    cudaGetSymbolAddress((void**)&sum, g_sum);
    cudaGetSymbolAddress((void**)&sq, g_sq);
    cudaGetSymbolAddress((void**)&mean, g_mean);
    cudaGetSymbolAddress((void**)&rstd, g_rstd);
    cudaGetSymbolAddress((void**)&cst6, g_const6);

    zero_kernel<<<cdiv(BATCH * 1024, 256), 256>>>();

    // L1: x(2) -> z1(64)
    kan_gemm<true, false, false><<<dim3(1, 256), 256>>>(
        x, w1, nullptr, nullptr, z1, sum + 0, sq + 0, nullptr, 2, 64);
    finalize_kernel<<<1, 64>>>(sum + 0, sq + 0, mean + 0, rstd + 0, 64);

    // L2: z1(64) -> z2(64)
    kan_gemm<false, false, false><<<dim3(1, 256), 256>>>(
        z1, w2, mean + 0, rstd + 0, z2, sum + 64, sq + 64, nullptr, 64, 64);
    finalize_kernel<<<1, 64>>>(sum + 64, sq + 64, mean + 64, rstd + 64, 64);

    // L3: z2(64) -> z3(64)
    kan_gemm<false, false, false><<<dim3(1, 256), 256>>>(
        z2, w3, mean + 64, rstd + 64, z3, sum + 128, sq + 128, nullptr, 64, 64);
    finalize_kernel<<<1, 64>>>(sum + 128, sq + 128, mean + 128, rstd + 128, 64);

    // L4: z3(64) -> z4(128)
    kan_gemm<false, false, false><<<dim3(2, 256), 256>>>(
        z3, w4, mean + 128, rstd + 128, z4, sum + 192, sq + 192, nullptr, 64, 128);
    finalize_kernel<<<2, 64>>>(sum + 192, sq + 192, mean + 192, rstd + 192, 128);

    // L5: z4(128) -> z5(1024)
    kan_gemm<false, false, false><<<dim3(16, 256), 256>>>(
        z4, w5, mean + 192, rstd + 192, z5, sum + 320, sq + 320, nullptr, 128, 1024);
    maxpool5_kernel<<<dim3(32, 8), 256>>>();
    finalize_kernel<<<16, 64>>>(sum + 320, sq + 320, mean + 320, rstd + 320, 1024);

    // gf constant contribution to layer 6 (per-batch GEMM, 32 x 4096 x 512)
    const6_kernel<<<dim3(8, 32), 64>>>(w6);

    // L6: local z2(64) -> z6(512), accumulators initialized with const6
    kan_gemm<false, false, true><<<dim3(8, 256), 256>>>(
        z2, w6, mean + 64, rstd + 64, z6, sum + 1344, sq + 1344, cst6, 64, 512);
    finalize_kernel<<<8, 64>>>(sum + 1344, sq + 1344, mean + 1344, rstd + 1344, 512);

    // L7: z6(512) -> z7(256)
    kan_gemm<false, false, false><<<dim3(4, 256), 256>>>(
        z6, w7, mean + 1344, rstd + 1344, z7, sum + 1856, sq + 1856, nullptr, 512, 256);
    finalize_kernel<<<4, 64>>>(sum + 1856, sq + 1856, mean + 1856, rstd + 1856, 256);

    // L8: z7(256) -> z8(128)
    kan_gemm<false, false, false><<<dim3(2, 256), 256>>>(
        z7, w8, mean + 1856, rstd + 1856, z8, sum + 2112, sq + 2112, nullptr, 256, 128);
    finalize_kernel<<<2, 64>>>(sum + 2112, sq + 2112, mean + 2112, rstd + 2112, 128);

    // L9: z8(128) -> z9(128)
    kan_gemm<false, false, false><<<dim3(2, 256), 256>>>(
        z8, w9, mean + 2112, rstd + 2112, z9, sum + 2240, sq + 2240, nullptr, 128, 128);
    finalize_kernel<<<2, 64>>>(sum + 2240, sq + 2240, mean + 2240, rstd + 2240, 128);

    // L10: z9(128) -> out (B, 3, N), no BN
    kan_gemm<false, true, false><<<dim3(1, 256), 256>>>(
        z9, w10, mean + 2240, rstd + 2240, outp, nullptr, nullptr, nullptr, 128, 3);
}

// round 7
// speedup vs baseline: 1.0686x; 1.0686x over previous
#include <cuda_runtime.h>
#include <cstddef>

#define NPTS 1024
#define BATCH 32
#define MTOT 32768
#define EPS_BN 1e-5f

// ---------------- static scratch (no allocations allowed) ----------------
__device__ float g_z1[(size_t)MTOT * 64];
__device__ float g_z2[(size_t)MTOT * 64];
__device__ float g_z3[(size_t)MTOT * 64];
__device__ float g_z4[(size_t)MTOT * 128];
// z5 is never materialized: max-pool + stats are fused into the L5 GEMM epilogue
__device__ float g_z6[(size_t)MTOT * 512];
__device__ float g_z7[(size_t)MTOT * 256];
__device__ float g_z8[(size_t)MTOT * 128];
__device__ float g_z9[(size_t)MTOT * 128];

// per-channel stats, packed by layer offset:
// L1:0(64) L2:64 L3:128 L4:192(128) L5:320(1024) L6:1344(512) L7:1856(256) L8:2112(128) L9:2240(128) -> 2368
__device__ float g_sum[2368];
__device__ float g_sq[2368];
__device__ float g_mean[2368];
__device__ float g_rstd[2368];

__device__ unsigned g_max5[BATCH * 1024];   // order-monotone uint-mapped float max
__device__ float g_const6[BATCH * 512];     // per-batch gf contribution to layer 6

// ---------------- helpers ----------------
__device__ __forceinline__ float fast_tanh(float x) {
    // tanh(x) = 1 - 2/(exp(2x)+1); ex2.approx + rcp.approx, rel err ~1e-6
    float e, r;
    asm("ex2.approx.f32 %0, %1;" : "=f"(e) : "f"(x * 2.8853900817779268f)); // 2*log2(e)
    asm("rcp.approx.f32 %0, %1;" : "=f"(r) : "f"(e + 1.0f));
    return 1.0f - 2.0f * r;
}

// Jacobi polys, degree 3, a=b=1 (exact constants from the reference recurrence)
__device__ __forceinline__ void jacobi4(float t, float& p0, float& p1, float& p2, float& p3) {
    p0 = 1.0f;
    p1 = 2.0f * t;
    p2 = 1.875f * t * p1 - 0.75f;
    p3 = 1.8666666666666667f * t * p2 - 0.8f * p1;
}

__device__ __forceinline__ unsigned fmap(float f) {
    unsigned u = __float_as_uint(f);
    return (u & 0x80000000u) ? ~u : (u | 0x80000000u);
}
__device__ __forceinline__ float funmap(unsigned u) {
    return (u & 0x80000000u) ? __uint_as_float(u & 0x7fffffffu) : __uint_as_float(~u);
}

union F2 {
    float2 f;
    unsigned long long u;
};

__device__ __forceinline__ void fma2(F2& d, const F2& a, const F2& b) {
    asm("fma.rn.f32x2 %0, %1, %2, %0;" : "+l"(d.u) : "l"(a.u), "l"(b.u));
}

// ---------------- kernels ----------------
__global__ void zero_kernel() {
    int i = blockIdx.x * 256 + threadIdx.x;
    if (i < 2368) { g_sum[i] = 0.f; g_sq[i] = 0.f; }
    if (i < BATCH * 1024) g_max5[i] = 0u;  // 0 < fmap(any finite float)
}

__global__ void finalize_kernel(const float* __restrict__ s, const float* __restrict__ q,
                                float* __restrict__ mean, float* __restrict__ rstd, int C) {
    int i = blockIdx.x * 64 + threadIdx.x;
    if (i < C) {
        float m = s[i] * (1.0f / 32768.0f);
        float v = q[i] * (1.0f / 32768.0f) - m * m;
        mean[i] = m;
        rstd[i] = rsqrtf(v + EPS_BN);
    }
}

// const6[b][o] = sum_{i in [0,1024)} phi(tanh(BN5(max5[b][i]))) . w6[64+i][o][:]
// grid (8 o-tiles, 8 b-tiles), 64 threads; 4 batches per block => w6 L2 traffic 64MB
__global__ void const6_kernel(const float* __restrict__ w6) {
    __shared__ float sb[4][256][4];   // 16KB staged basis
    const int b0 = blockIdx.y * 4;
    const int o = blockIdx.x * 64 + threadIdx.x;
    const float* mean5 = &g_mean[320];
    const float* rstd5 = &g_rstd[320];
    float acc[4] = {0.f, 0.f, 0.f, 0.f};
    for (int i0 = 0; i0 < 1024; i0 += 256) {
        for (int e = threadIdx.x; e < 1024; e += 64) {
            int bj = e >> 8, i = e & 255;
            float f = funmap(g_max5[(b0 + bj) * 1024 + i0 + i]);
            float t = fast_tanh((f - mean5[i0 + i]) * rstd5[i0 + i]);
            float p0, p1, p2, p3;
            jacobi4(t, p0, p1, p2, p3);
            sb[bj][i][0] = p0; sb[bj][i][1] = p1;
            sb[bj][i][2] = p2; sb[bj][i][3] = p3;
        }
        __syncthreads();
#pragma unroll 4
        for (int i = 0; i < 256; i++) {
            float4 wv = *reinterpret_cast<const float4*>(&w6[((size_t)(64 + i0 + i) * 512 + o) * 4]);
#pragma unroll
            for (int bj = 0; bj < 4; bj++)
                acc[bj] += sb[bj][i][0] * wv.x + sb[bj][i][1] * wv.y +
                           sb[bj][i][2] * wv.z + sb[bj][i][3] * wv.w;
        }
        __syncthreads();
    }
#pragma unroll
    for (int bj = 0; bj < 4; bj++) g_const6[(b0 + bj) * 512 + o] = acc[bj];
}

// ======================= packed-f32x2 KAN GEMM (heavy layers) =======================
// BM=256, BN=128, BK=32 (8 input channels), 256 threads, per-thread tile 16x8
// packed as 8 row-pairs x 8 cols of fma.rn.f32x2.
// Requires: C_in % 8 == 0, C_out % 128 == 0. BN applied to input (mean/rstd).
// MAXPOOL: skip output store; per-(batch,col) max -> atomicMax (+ stats).
// HASCONST: init accumulators with cst[b][col] (gf contribution for layer 6).
template <bool MAXPOOL, bool HASCONST>
__global__ __launch_bounds__(256) void kan_gemm2(
    const float* __restrict__ in, const float* __restrict__ w,
    const float* __restrict__ mean, const float* __restrict__ rstd,
    float* __restrict__ out, float* __restrict__ ssum, float* __restrict__ ssq,
    const float* __restrict__ cst, int C_in, int C_out)
{
    __shared__ float As[32][256];   // 32KB  [k=ch*4+d][row]
    __shared__ float Bs[32][128];   // 16KB  [k][o]

    const int tid = threadIdx.x;
    const int tcol = tid & 15;      // 16 col groups * 8
    const int trow = tid >> 4;      // 16 row groups * 16
    const int m0 = blockIdx.y * 256;
    const int n0 = blockIdx.x * 128;
    const int b = m0 >> 10;         // 256-row tiles never cross batch (1024 % 256 == 0)

    F2 acc[8][8];
    if (HASCONST) {
#pragma unroll
        for (int c = 0; c < 8; c++) {
            float v = cst[b * C_out + n0 + tcol * 8 + c];
#pragma unroll
            for (int rp = 0; rp < 8; rp++) acc[rp][c].f = make_float2(v, v);
        }
    } else {
#pragma unroll
        for (int rp = 0; rp < 8; rp++)
#pragma unroll
            for (int c = 0; c < 8; c++) acc[rp][c].f = make_float2(0.f, 0.f);
    }

    const int numKT = C_in >> 3;
    for (int kt = 0; kt < numKT; kt++) {
        const int ch0 = kt * 8;

        // ---- A tile: 256 rows x 8 channels, basis-expand. 2 threads per row. ----
#pragma unroll
        for (int p = 0; p < 2; p++) {
            const int row = (tid >> 1) + p * 128;
            const int chq = (tid & 1) * 4;
            const float4 v4 =
                *reinterpret_cast<const float4*>(&in[(size_t)(m0 + row) * C_in + ch0 + chq]);
            const float vv[4] = {v4.x, v4.y, v4.z, v4.w};
#pragma unroll
            for (int j = 0; j < 4; j++) {
                int cc = ch0 + chq + j;
                float t = fast_tanh((vv[j] - mean[cc]) * rstd[cc]);
                float p0, p1, p2, p3;
                jacobi4(t, p0, p1, p2, p3);
                int k = (chq + j) * 4;
                As[k + 0][row] = p0; As[k + 1][row] = p1;
                As[k + 2][row] = p2; As[k + 3][row] = p3;
            }
        }

        // ---- B tile: w[(ch0+ch), n0+o, 0..3] as float4; 8 ch x 128 cols ----
#pragma unroll
        for (int p = 0; p < 4; p++) {
            int f = tid + p * 256;            // float4 index 0..1023
            int ch = f >> 7;
            int o = f & 127;
            float4 wv = *reinterpret_cast<const float4*>(
                &w[((size_t)(ch0 + ch) * C_out + n0 + o) * 4]);
            int k = ch * 4;
            Bs[k + 0][o] = wv.x; Bs[k + 1][o] = wv.y;
            Bs[k + 2][o] = wv.z; Bs[k + 3][o] = wv.w;
        }
        __syncthreads();

#pragma unroll 8
        for (int k = 0; k < 32; k++) {
            F2 a2[8];
#pragma unroll
            for (int i = 0; i < 8; i++)
                a2[i].f = *reinterpret_cast<const float2*>(&As[k][trow * 16 + 2 * i]);
            float4 b0v = *reinterpret_cast<const float4*>(&Bs[k][tcol * 8]);
            float4 b1v = *reinterpret_cast<const float4*>(&Bs[k][tcol * 8 + 4]);
            const float bv[8] = {b0v.x, b0v.y, b0v.z, b0v.w, b1v.x, b1v.y, b1v.z, b1v.w};
#pragma unroll
            for (int c = 0; c < 8; c++) {
                F2 bb; bb.f = make_float2(bv[c], bv[c]);
#pragma unroll
                for (int rp = 0; rp < 8; rp++) fma2(acc[rp][c], a2[rp], bb);
            }
        }
        __syncthreads();
    }

    // ---- output store (row-major out[m][o]) ----
    if (!MAXPOOL) {
#pragma unroll
        for (int r = 0; r < 16; r++) {
            const int rp = r >> 1;
            const bool hi = r & 1;
            float4 o0, o1;
            o0.x = hi ? acc[rp][0].f.y : acc[rp][0].f.x;
            o0.y = hi ? acc[rp][1].f.y : acc[rp][1].f.x;
            o0.z = hi ? acc[rp][2].f.y : acc[rp][2].f.x;
            o0.w = hi ? acc[rp][3].f.y : acc[rp][3].f.x;
            o1.x = hi ? acc[rp][4].f.y : acc[rp][4].f.x;
            o1.y = hi ? acc[rp][5].f.y : acc[rp][5].f.x;
            o1.z = hi ? acc[rp][6].f.y : acc[rp][6].f.x;
            o1.w = hi ? acc[rp][7].f.y : acc[rp][7].f.x;
            size_t base = (size_t)(m0 + trow * 16 + r) * C_out + n0 + tcol * 8;
            *reinterpret_cast<float4*>(&out[base]) = o0;
            *reinterpret_cast<float4*>(&out[base + 4]) = o1;
        }
    }

    // ---- stats (+ max) reductions; reuse As (and Bs) as scratch ----
    float s[8], q[8], mx[8];
#pragma unroll
    for (int c = 0; c < 8; c++) {
        s[c] = 0.f; q[c] = 0.f; mx[c] = -3.4e38f;
#pragma unroll
        for (int rp = 0; rp < 8; rp++) {
            float x = acc[rp][c].f.x, y = acc[rp][c].f.y;
            s[c] += x + y;
            q[c] += x * x + y * y;
            if (MAXPOOL) mx[c] = fmaxf(mx[c], fmaxf(x, y));
        }
    }
    float* redS = &As[0][0];          // [16][128]
    float* redQ = &As[0][0] + 2048;   // [16][128]
    float* redM = &Bs[0][0];          // [16][128]
#pragma unroll
    for (int c = 0; c < 8; c++) {
        redS[trow * 128 + tcol * 8 + c] = s[c];
        redQ[trow * 128 + tcol * 8 + c] = q[c];
        if (MAXPOOL) redM[trow * 128 + tcol * 8 + c] = mx[c];
    }
    __syncthreads();
    if (tid < 128) {
        float ts = 0.f, tq = 0.f, tm = -3.4e38f;
#pragma unroll
        for (int r = 0; r < 16; r++) {
            ts += redS[r * 128 + tid];
            tq += redQ[r * 128 + tid];
            if (MAXPOOL) tm = fmaxf(tm, redM[r * 128 + tid]);
        }
        atomicAdd(&ssum[n0 + tid], ts);
        atomicAdd(&ssq[n0 + tid], tq);
        if (MAXPOOL) atomicMax(&g_max5[b * 1024 + n0 + tid], fmap(tm));
    }
}

// ======================= original GEMM (small/edge layers) =======================
// FIRST: input is x with layout (B, C_in, N), no BN on input.
// LAST:  output layout (B, C_out, N), no stats.
template <bool FIRST, bool LAST>
__global__ __launch_bounds__(256) void kan_gemm(
    const float* __restrict__ in, const float* __restrict__ w,
    const float* __restrict__ mean, const float* __restrict__ rstd,
    float* __restrict__ out, float* __restrict__ ssum, float* __restrict__ ssq,
    int C_in, int C_out)
{
    __shared__ float As[32][128];
    __shared__ float Bs[32][64];
    __shared__ float redS[16][64];
    __shared__ float redQ[16][64];

    const int tid = threadIdx.x;
    const int tcol = tid & 15, trow = tid >> 4;
    const int m0 = blockIdx.y * 128;
    const int n0 = blockIdx.x * 64;

    float acc[8][4];
#pragma unroll
    for (int r = 0; r < 8; r++)
#pragma unroll
        for (int c = 0; c < 4; c++) acc[r][c] = 0.f;

    const int numKT = (C_in + 7) >> 3;
    for (int kt = 0; kt < numKT; kt++) {
        const int ch0 = kt * 8;
        if (FIRST) {
            const int ch = tid & 7;
            const int rb = tid >> 3;
#pragma unroll
            for (int p = 0; p < 4; p++) {
                int row = rb + p * 32;
                float p0 = 0.f, p1 = 0.f, p2 = 0.f, p3 = 0.f;
                if (ch0 + ch < C_in) {
                    int m = m0 + row;
                    float v = in[(m >> 10) * (2 * NPTS) + (ch0 + ch) * NPTS + (m & (NPTS - 1))];
                    float t = fast_tanh(v);
                    jacobi4(t, p0, p1, p2, p3);
                }
                int k = ch * 4;
                As[k + 0][row] = p0; As[k + 1][row] = p1;
                As[k + 2][row] = p2; As[k + 3][row] = p3;
            }
        } else {
            const int row = tid >> 1;
            const int chq = (tid & 1) * 4;
            const float4 v4 =
                *reinterpret_cast<const float4*>(&in[(size_t)(m0 + row) * C_in + ch0 + chq]);
            const float vv[4] = {v4.x, v4.y, v4.z, v4.w};
#pragma unroll
            for (int j = 0; j < 4; j++) {
                int cc = ch0 + chq + j;
                float t = fast_tanh((vv[j] - mean[cc]) * rstd[cc]);
                float p0, p1, p2, p3;
                jacobi4(t, p0, p1, p2, p3);
                int k = (chq + j) * 4;
                As[k + 0][row] = p0; As[k + 1][row] = p1;
                As[k + 2][row] = p2; As[k + 3][row] = p3;
            }
        }
#pragma unroll
        for (int p = 0; p < 2; p++) {
            int f = tid + p * 256;
            int ch = f >> 6;
            int o = f & 63;
            int cc = ch0 + ch;
            int col = n0 + o;
            float4 wv = make_float4(0.f, 0.f, 0.f, 0.f);
            if (cc < C_in && col < C_out)
                wv = *reinterpret_cast<const float4*>(&w[((size_t)cc * C_out + col) * 4]);
            int k = ch * 4;
            Bs[k + 0][o] = wv.x; Bs[k + 1][o] = wv.y;
            Bs[k + 2][o] = wv.z; Bs[k + 3][o] = wv.w;
        }
        __syncthreads();

#pragma unroll
        for (int k = 0; k < 32; k++) {
            float a[8], bv[4];
#pragma unroll
            for (int r = 0; r < 8; r++) a[r] = As[k][trow * 8 + r];
#pragma unroll
            for (int c = 0; c < 4; c++) bv[c] = Bs[k][tcol * 4 + c];
#pragma unroll
            for (int r = 0; r < 8; r++)
#pragma unroll
                for (int c = 0; c < 4; c++) acc[r][c] = fmaf(a[r], bv[c], acc[r][c]);
        }
        __syncthreads();
    }

    if (LAST) {
#pragma unroll
        for (int r = 0; r < 8; r++) {
            int m = m0 + trow * 8 + r;
            int bb = m >> 10, n = m & (NPTS - 1);
#pragma unroll
            for (int c = 0; c < 4; c++) {
                int col = n0 + tcol * 4 + c;
                if (col < C_out) out[((size_t)bb * C_out + col) * NPTS + n] = acc[r][c];
            }
        }
    } else {
#pragma unroll
        for (int r = 0; r < 8; r++) {
            size_t m = m0 + trow * 8 + r;
            float4 v = make_float4(acc[r][0], acc[r][1], acc[r][2], acc[r][3]);
            *reinterpret_cast<float4*>(&out[m * C_out + n0 + tcol * 4]) = v;
        }
        float s[4] = {0, 0, 0, 0}, q[4] = {0, 0, 0, 0};
#pragma unroll
        for (int r = 0; r < 8; r++)
#pragma unroll
            for (int c = 0; c < 4; c++) {
                s[c] += acc[r][c];
                q[c] += acc[r][c] * acc[r][c];
            }
#pragma unroll
        for (int c = 0; c < 4; c++) {
            redS[trow][tcol * 4 + c] = s[c];
            redQ[trow][tcol * 4 + c] = q[c];
        }
        __syncthreads();
        if (tid < 64 && (n0 + tid) < C_out) {
            float ts = 0.f, tq = 0.f;
#pragma unroll
            for (int r = 0; r < 16; r++) { ts += redS[r][tid]; tq += redQ[r][tid]; }
            atomicAdd(&ssum[n0 + tid], ts);
            atomicAdd(&ssq[n0 + tid], tq);
        }
    }
}

// ---------------- launch ----------------
static inline int cdiv(int a, int b) { return (a + b - 1) / b; }

extern "C" void kernel_launch(void* const* d_in, const int* in_sizes, int n_in,
                              void* d_out, int out_size) {
    (void)in_sizes; (void)n_in; (void)out_size;
    const float* x   = (const float*)d_in[0];
    const float* w1  = (const float*)d_in[1];
    const float* w2  = (const float*)d_in[2];
    const float* w3  = (const float*)d_in[3];
    const float* w4  = (const float*)d_in[4];
    const float* w5  = (const float*)d_in[5];
    const float* w6  = (const float*)d_in[6];
    const float* w7  = (const float*)d_in[7];
    const float* w8  = (const float*)d_in[8];
    const float* w9  = (const float*)d_in[9];
    const float* w10 = (const float*)d_in[10];
    float* outp = (float*)d_out;

    float *z1, *z2, *z3, *z4, *z6, *z7, *z8, *z9;
    float *sum, *sq, *mean, *rstd, *cst6;
    cudaGetSymbolAddress((void**)&z1, g_z1);
    cudaGetSymbolAddress((void**)&z2, g_z2);
    cudaGetSymbolAddress((void**)&z3, g_z3);
    cudaGetSymbolAddress((void**)&z4, g_z4);
    cudaGetSymbolAddress((void**)&z6, g_z6);
    cudaGetSymbolAddress((void**)&z7, g_z7);
    cudaGetSymbolAddress((void**)&z8, g_z8);
    cudaGetSymbolAddress((void**)&z9, g_z9);
    cudaGetSymbolAddress((void**)&sum, g_sum);
    cudaGetSymbolAddress((void**)&sq, g_sq);
    cudaGetSymbolAddress((void**)&mean, g_mean);
    cudaGetSymbolAddress((void**)&rstd, g_rstd);
    cudaGetSymbolAddress((void**)&cst6, g_const6);

    zero_kernel<<<cdiv(BATCH * 1024, 256), 256>>>();

    // L1: x(2) -> z1(64)   [FIRST, N=64]
    kan_gemm<true, false><<<dim3(1, 256), 256>>>(
        x, w1, nullptr, nullptr, z1, sum + 0, sq + 0, 2, 64);
    finalize_kernel<<<1, 64>>>(sum + 0, sq + 0, mean + 0, rstd + 0, 64);

    // L2: z1(64) -> z2(64)
    kan_gemm<false, false><<<dim3(1, 256), 256>>>(
        z1, w2, mean + 0, rstd + 0, z2, sum + 64, sq + 64, 64, 64);
    finalize_kernel<<<1, 64>>>(sum + 64, sq + 64, mean + 64, rstd + 64, 64);

    // L3: z2(64) -> z3(64)
    kan_gemm<false, false><<<dim3(1, 256), 256>>>(
        z2, w3, mean + 64, rstd + 64, z3, sum + 128, sq + 128, 64, 64);
    finalize_kernel<<<1, 64>>>(sum + 128, sq + 128, mean + 128, rstd + 128, 64);

    // L4: z3(64) -> z4(128)   [packed]
    kan_gemm2<false, false><<<dim3(1, 128), 256>>>(
        z3, w4, mean + 128, rstd + 128, z4, sum + 192, sq + 192, nullptr, 64, 128);
    finalize_kernel<<<2, 64>>>(sum + 192, sq + 192, mean + 192, rstd + 192, 128);

    // L5: z4(128) -> (maxpool + stats only, z5 never stored)   [packed, MAXPOOL]
    kan_gemm2<true, false><<<dim3(8, 128), 256>>>(
        z4, w5, mean + 192, rstd + 192, nullptr, sum + 320, sq + 320, nullptr, 128, 1024);
    finalize_kernel<<<16, 64>>>(sum + 320, sq + 320, mean + 320, rstd + 320, 1024);

    // gf constant contribution to layer 6
    const6_kernel<<<dim3(8, 8), 64>>>(w6);

    // L6: local z2(64) -> z6(512), accumulators initialized with const6   [packed, HASCONST]
    kan_gemm2<false, true><<<dim3(4, 128), 256>>>(
        z2, w6, mean + 64, rstd + 64, z6, sum + 1344, sq + 1344, cst6, 64, 512);
    finalize_kernel<<<8, 64>>>(sum + 1344, sq + 1344, mean + 1344, rstd + 1344, 512);

    // L7: z6(512) -> z7(256)   [packed]
    kan_gemm2<false, false><<<dim3(2, 128), 256>>>(
        z6, w7, mean + 1344, rstd + 1344, z7, sum + 1856, sq + 1856, nullptr, 512, 256);
    finalize_kernel<<<4, 64>>>(sum + 1856, sq + 1856, mean + 1856, rstd + 1856, 256);

    // L8: z7(256) -> z8(128)   [packed]
    kan_gemm2<false, false><<<dim3(1, 128), 256>>>(
        z7, w8, mean + 1856, rstd + 1856, z8, sum + 2112, sq + 2112, nullptr, 256, 128);
    finalize_kernel<<<2, 64>>>(sum + 2112, sq + 2112, mean + 2112, rstd + 2112, 128);

    // L9: z8(128) -> z9(128)   [packed]
    kan_gemm2<false, false><<<dim3(1, 128), 256>>>(
        z8, w9, mean + 2112, rstd + 2112, z9, sum + 2240, sq + 2240, nullptr, 128, 128);
    finalize_kernel<<<2, 64>>>(sum + 2240, sq + 2240, mean + 2240, rstd + 2240, 128);

    // L10: z9(128) -> out (B, 3, N), no BN   [LAST]
    kan_gemm<false, true><<<dim3(1, 256), 256>>>(
        z9, w10, mean + 2240, rstd + 2240, outp, nullptr, nullptr, 128, 3);
}

// round 9
// speedup vs baseline: 1.8007x; 1.6851x over previous
#include <cuda_runtime.h>
#include <cstddef>
#include <cstdint>

#define NPTS 1024
#define BATCH 32
#define MTOT 32768
#define EPS_BN 1e-5f

// ---------------- static scratch (no allocations allowed) ----------------
__device__ float g_z1[(size_t)MTOT * 64];
__device__ float g_z2[(size_t)MTOT * 64];
__device__ float g_z3[(size_t)MTOT * 64];
__device__ float g_z4[(size_t)MTOT * 128];
// z5 is never materialized: max-pool + stats are fused into the L5 GEMM epilogue
__device__ float g_z6[(size_t)MTOT * 512];
__device__ float g_z7[(size_t)MTOT * 256];
__device__ float g_z8[(size_t)MTOT * 128];
__device__ float g_z9[(size_t)MTOT * 128];

// per-channel stats, packed by layer offset:
// L1:0(64) L2:64 L3:128 L4:192(128) L5:320(1024) L6:1344(512) L7:1856(256) L8:2112(128) L9:2240(128) -> 2368
__device__ float g_sum[2368];
__device__ float g_sq[2368];
__device__ float g_mean[2368];
__device__ float g_rstd[2368];

__device__ unsigned g_max5[BATCH * 1024];   // order-monotone uint-mapped float max
__device__ float g_const6[BATCH * 512];     // per-batch gf contribution to layer 6

// ---------------- helpers ----------------
__device__ __forceinline__ float fast_tanh(float x) {
    // tanh(x) = 1 - 2/(exp(2x)+1); ex2.approx + rcp.approx, rel err ~1e-6
    float e, r;
    asm("ex2.approx.f32 %0, %1;" : "=f"(e) : "f"(x * 2.8853900817779268f)); // 2*log2(e)
    asm("rcp.approx.f32 %0, %1;" : "=f"(r) : "f"(e + 1.0f));
    return 1.0f - 2.0f * r;
}

// Jacobi polys, degree 3, a=b=1 (exact constants from the reference recurrence)
__device__ __forceinline__ void jacobi4(float t, float& p0, float& p1, float& p2, float& p3) {
    p0 = 1.0f;
    p1 = 2.0f * t;
    p2 = 1.875f * t * p1 - 0.75f;
    p3 = 1.8666666666666667f * t * p2 - 0.8f * p1;
}

__device__ __forceinline__ unsigned fmap(float f) {
    unsigned u = __float_as_uint(f);
    return (u & 0x80000000u) ? ~u : (u | 0x80000000u);
}
__device__ __forceinline__ float funmap(unsigned u) {
    return (u & 0x80000000u) ? __uint_as_float(u & 0x7fffffffu) : __uint_as_float(~u);
}

static __device__ __forceinline__ uint32_t smem_u32(const void* p) {
    uint32_t a;
    asm("{ .reg .u64 t; cvta.to.shared.u64 t, %1; cvt.u32.u64 %0, t; }" : "=r"(a) : "l"(p));
    return a;
}

__device__ __forceinline__ unsigned pack_bf16(float lo, float hi) {
    // result low 16 bits = bf16(lo), high = bf16(hi)
    unsigned r;
    asm("cvt.rn.bf16x2.f32 %0, %1, %2;" : "=r"(r) : "f"(hi), "f"(lo));
    return r;
}
// split 8 consecutive fp32 values into hi/lo bf16x2 quads (memory order preserved)
__device__ __forceinline__ void split8(const float* v, uint4& hi, uint4& lo) {
    unsigned h[4], l[4];
#pragma unroll
    for (int g = 0; g < 4; g++) {
        float a0 = v[2 * g], a1 = v[2 * g + 1];
        unsigned p = pack_bf16(a0, a1);
        float h0 = __uint_as_float(p << 16);
        float h1 = __uint_as_float(p & 0xffff0000u);
        h[g] = p;
        l[g] = pack_bf16(a0 - h0, a1 - h1);
    }
    hi = make_uint4(h[0], h[1], h[2], h[3]);
    lo = make_uint4(l[0], l[1], l[2], l[3]);
}

__device__ __forceinline__ void ldsm4(uint32_t addr, uint32_t* r) {
    asm volatile("ldmatrix.sync.aligned.m8n8.x4.shared.b16 {%0,%1,%2,%3}, [%4];"
                 : "=r"(r[0]), "=r"(r[1]), "=r"(r[2]), "=r"(r[3]) : "r"(addr));
}

__device__ __forceinline__ void mma16816(float* c, const uint32_t* a, uint32_t b0, uint32_t b1) {
    asm volatile(
        "mma.sync.aligned.m16n8k16.row.col.f32.bf16.bf16.f32 "
        "{%0,%1,%2,%3}, {%4,%5,%6,%7}, {%8,%9}, {%0,%1,%2,%3};"
        : "+f"(c[0]), "+f"(c[1]), "+f"(c[2]), "+f"(c[3])
        : "r"(a[0]), "r"(a[1]), "r"(a[2]), "r"(a[3]), "r"(b0), "r"(b1));
}

// SMEM layout of the tensor kernel (byte offsets from a 1024-aligned base)
#define OFF_AHI 0
#define OFF_ALO 16384
#define OFF_BHI 32768
#define OFF_BLO 49152
#define OFF_CST 66560                  // after the 128x130 fp32 epilogue scratch
#define SMEM_MMA (OFF_CST + 512 + 1024)

// ---------------- tiny kernels ----------------
__global__ void zero_kernel() {
    int i = blockIdx.x * 256 + threadIdx.x;
    if (i < 2368) { g_sum[i] = 0.f; g_sq[i] = 0.f; }
    if (i < BATCH * 1024) g_max5[i] = 0u;  // 0 < fmap(any finite float)
}

__global__ void finalize_kernel(const float* __restrict__ s, const float* __restrict__ q,
                                float* __restrict__ mean, float* __restrict__ rstd, int C) {
    int i = blockIdx.x * 64 + threadIdx.x;
    if (i < C) {
        float m = s[i] * (1.0f / 32768.0f);
        float v = q[i] * (1.0f / 32768.0f) - m * m;
        mean[i] = m;
        rstd[i] = rsqrtf(v + EPS_BN);
    }
}

// const6[b][o] = sum_{i in [0,1024)} phi(tanh(BN5(max5[b][i]))) . w6[64+i][o][:]
__global__ void const6_kernel(const float* __restrict__ w6) {
    __shared__ float sb[4][256][4];   // 16KB staged basis
    const int b0 = blockIdx.y * 4;
    const int o = blockIdx.x * 64 + threadIdx.x;
    const float* mean5 = &g_mean[320];
    const float* rstd5 = &g_rstd[320];
    float acc[4] = {0.f, 0.f, 0.f, 0.f};
    for (int i0 = 0; i0 < 1024; i0 += 256) {
        for (int e = threadIdx.x; e < 1024; e += 64) {
            int bj = e >> 8, i = e & 255;
            float f = funmap(g_max5[(b0 + bj) * 1024 + i0 + i]);
            float t = fast_tanh((f - mean5[i0 + i]) * rstd5[i0 + i]);
            float p0, p1, p2, p3;
            jacobi4(t, p0, p1, p2, p3);
            sb[bj][i][0] = p0; sb[bj][i][1] = p1;
            sb[bj][i][2] = p2; sb[bj][i][3] = p3;
        }
        __syncthreads();
#pragma unroll 4
        for (int i = 0; i < 256; i++) {
            float4 wv = *reinterpret_cast<const float4*>(&w6[((size_t)(64 + i0 + i) * 512 + o) * 4]);
#pragma unroll
            for (int bj = 0; bj < 4; bj++)
                acc[bj] += sb[bj][i][0] * wv.x + sb[bj][i][1] * wv.y +
                           sb[bj][i][2] * wv.z + sb[bj][i][3] * wv.w;
        }
        __syncthreads();
    }
#pragma unroll
    for (int bj = 0; bj < 4; bj++) g_const6[(b0 + bj) * 512 + o] = acc[bj];
}

// ======================= split-bf16 HMMA KAN GEMM (heavy layers) =======================
// BM=128 x BN=128, BK=64 (16 channels x 4 bases), 256 threads (8 warps, 2Mx4N grid).
// D = Ah*Bh^T + Ah*Bl^T + Al*Bh^T in fp32 accumulators via mma.sync.m16n8k16.bf16.
// Requires C_in % 16 == 0, C_out % 128 == 0. BN applied to input (mean/rstd).
template <bool MAXPOOL, bool HASCONST>
__global__ __launch_bounds__(256)
void kan_mma(const float* __restrict__ in, const float* __restrict__ w,
             const float* __restrict__ mean, const float* __restrict__ rstd,
             float* __restrict__ out, float* __restrict__ ssum, float* __restrict__ ssq,
             const float* __restrict__ cst, int C_in, int C_out)
{
    extern __shared__ char dsm[];
    const uint32_t raw32 = smem_u32(dsm);
    const uint32_t ab32 = (raw32 + 1023u) & ~1023u;
    char* ab = dsm + (ab32 - raw32);

    const int tid = threadIdx.x;
    const int lane = tid & 31;
    const int wid = tid >> 5;
    const int m0 = blockIdx.y * 128;
    const int n0 = blockIdx.x * 128;
    const int b = m0 >> 10;             // 128-row tiles never cross batch

    float* cst_s = reinterpret_cast<float*>(ab + OFF_CST);
    if (HASCONST && tid < 128) cst_s[tid] = cst[(size_t)b * C_out + n0 + tid];

    float acc[4][4][4];
#pragma unroll
    for (int mi = 0; mi < 4; mi++)
#pragma unroll
        for (int ni = 0; ni < 4; ni++)
#pragma unroll
            for (int r = 0; r < 4; r++) acc[mi][ni][r] = 0.f;

    const uint32_t AH = ab32 + OFF_AHI, AL = ab32 + OFF_ALO;
    const uint32_t BHa = ab32 + OFF_BHI, BLa = ab32 + OFF_BLO;

    const int mw = (wid >> 2) * 64;     // warp M offset (2 warps in M)
    const int nw = (wid & 3) * 32;      // warp N offset (4 warps in N)
    const int rof = (lane & 7) + ((lane >> 3) & 1) * 8;   // ldmatrix row-within-frag
    const int klo = (lane >> 4) * 16;                      // ldmatrix 16B chunk select
    const int rbase = ((rof >> 3) << 10) + ((rof & 7) << 7);
    const int rxor = (rof & 7) << 4;

    const int numKT = C_in >> 4;
    for (int kt = 0; kt < numKT; kt++) {
        const int ch0 = kt * 16;

        // ---- A producer: 128 rows x 16 channels -> basis -> bf16 hi/lo, SW128 ----
        {
            const int row = tid >> 1;
            const int chq = (tid & 1) * 8;
            const size_t base = (size_t)(m0 + row) * C_in + ch0 + chq;
            const float4 v4a = *reinterpret_cast<const float4*>(&in[base]);
            const float4 v4b = *reinterpret_cast<const float4*>(&in[base + 4]);
            const float vv[8] = {v4a.x, v4a.y, v4a.z, v4a.w, v4b.x, v4b.y, v4b.z, v4b.w};
            float vals[32];
#pragma unroll
            for (int j = 0; j < 8; j++) {
                const int cc = ch0 + chq + j;
                float t = fast_tanh((vv[j] - mean[cc]) * rstd[cc]);
                jacobi4(t, vals[j * 4 + 0], vals[j * 4 + 1], vals[j * 4 + 2], vals[j * 4 + 3]);
            }
            const uint32_t offr = ((uint32_t)(row >> 3) << 10) + ((uint32_t)(row & 7) << 7);
            const uint32_t rx = (uint32_t)(row & 7) << 4;
#pragma unroll
            for (int g = 0; g < 4; g++) {
                uint4 hi, lo;
                split8(vals + 8 * g, hi, lo);
                const uint32_t cb = (uint32_t)chq * 8 + g * 16;
                const uint32_t sw = offr + (cb ^ rx);
                *reinterpret_cast<uint4*>(ab + OFF_AHI + sw) = hi;
                *reinterpret_cast<uint4*>(ab + OFF_ALO + sw) = lo;
            }
        }

        // ---- B producer: w[ch][n0+n][0..3] -> bf16 hi/lo, SW128 (rows = out col) ----
        {
            const int n = tid & 127;
            const int chh = (tid >> 7) * 8;
            const uint32_t offr = ((uint32_t)(n >> 3) << 10) + ((uint32_t)(n & 7) << 7);
            const uint32_t rx = (uint32_t)(n & 7) << 4;
            const size_t chstride = (size_t)C_out * 4;
            const size_t wb = ((size_t)(ch0 + chh) * C_out + (n0 + n)) * 4;
#pragma unroll
            for (int cp = 0; cp < 4; cp++) {
                float4 w0 = *reinterpret_cast<const float4*>(&w[wb + (size_t)(2 * cp) * chstride]);
                float4 w1 = *reinterpret_cast<const float4*>(&w[wb + (size_t)(2 * cp + 1) * chstride]);
                const float v[8] = {w0.x, w0.y, w0.z, w0.w, w1.x, w1.y, w1.z, w1.w};
                uint4 hi, lo;
                split8(v, hi, lo);
                const uint32_t cb = (uint32_t)chh * 8 + cp * 16;
                const uint32_t sw = offr + (cb ^ rx);
                *reinterpret_cast<uint4*>(ab + OFF_BHI + sw) = hi;
                *reinterpret_cast<uint4*>(ab + OFF_BLO + sw) = lo;
            }
        }
        __syncthreads();

        // ---- HMMA: 4 k16 chunks x (AhBh + AhBl + AlBh) ----
#pragma unroll
        for (int ks = 0; ks < 4; ks++) {
            const uint32_t kb = ks * 32;
            uint32_t ah[4][4], al[4][4];
#pragma unroll
            for (int mi = 0; mi < 4; mi++) {
                const uint32_t off = ((uint32_t)((mw + mi * 16) >> 3) << 10) + rbase
                                     + ((kb + klo) ^ rxor);
                ldsm4(AH + off, ah[mi]);
                ldsm4(AL + off, al[mi]);
            }
            uint32_t bh[2][4], bl[2][4];
#pragma unroll
            for (int nj = 0; nj < 2; nj++) {
                const uint32_t off = ((uint32_t)((nw + nj * 16) >> 3) << 10) + rbase
                                     + ((kb + klo) ^ rxor);
                ldsm4(BHa + off, bh[nj]);
                ldsm4(BLa + off, bl[nj]);
            }
#pragma unroll
            for (int mi = 0; mi < 4; mi++)
#pragma unroll
                for (int ni = 0; ni < 4; ni++) {
                    const int nj = ni >> 1, s = ni & 1;
                    mma16816(acc[mi][ni], ah[mi], bh[nj][s], bh[nj][s + 2]);
                    mma16816(acc[mi][ni], ah[mi], bl[nj][s], bl[nj][s + 2]);
                    mma16816(acc[mi][ni], al[mi], bh[nj][s], bh[nj][s + 2]);
                }
        }
        __syncthreads();
    }

    // ---- epilogue: frags -> smem [128][130] fp32, then coalesced store + stats ----
    float* scr = reinterpret_cast<float*>(ab);
#pragma unroll
    for (int mi = 0; mi < 4; mi++)
#pragma unroll
        for (int ni = 0; ni < 4; ni++)
#pragma unroll
            for (int r = 0; r < 4; r++) {
                const int ml = mw + mi * 16 + (lane >> 2) + (r >> 1) * 8;
                const int nl = nw + ni * 8 + (lane & 3) * 2 + (r & 1);
                float v = acc[mi][ni][r];
                if (HASCONST) v += cst_s[nl];
                scr[ml * 130 + nl] = v;
            }
    __syncthreads();

    if (!MAXPOOL) {
#pragma unroll 4
        for (int i = 0; i < 16; i++) {
            const int r = wid * 16 + i;
            const float* row = &scr[r * 130 + lane * 4];
            *reinterpret_cast<float4*>(&out[(size_t)(m0 + r) * C_out + n0 + lane * 4]) =
                make_float4(row[0], row[1], row[2], row[3]);
        }
    }
    if (tid < 128) {
        float s = 0.f, q = 0.f, mx = -3.4e38f;
        for (int r = 0; r < 128; r++) {
            float v = scr[r * 130 + tid];
            s += v; q += v * v;
            if (MAXPOOL) mx = fmaxf(mx, v);
        }
        atomicAdd(&ssum[n0 + tid], s);
        atomicAdd(&ssq[n0 + tid], q);
        if (MAXPOOL) atomicMax(&g_max5[b * 1024 + n0 + tid], fmap(mx));
    }
}

// ======================= scalar GEMM (edge layers: L1, L2, L3, L10) =======================
template <bool FIRST, bool LAST>
__global__ __launch_bounds__(256) void kan_gemm(
    const float* __restrict__ in, const float* __restrict__ w,
    const float* __restrict__ mean, const float* __restrict__ rstd,
    float* __restrict__ out, float* __restrict__ ssum, float* __restrict__ ssq,
    int C_in, int C_out)
{
    __shared__ float As[32][128];
    __shared__ float Bs[32][64];
    __shared__ float redS[16][64];
    __shared__ float redQ[16][64];

    const int tid = threadIdx.x;
    const int tcol = tid & 15, trow = tid >> 4;
    const int m0 = blockIdx.y * 128;
    const int n0 = blockIdx.x * 64;

    float acc[8][4];
#pragma unroll
    for (int r = 0; r < 8; r++)
#pragma unroll
        for (int c = 0; c < 4; c++) acc[r][c] = 0.f;

    const int numKT = (C_in + 7) >> 3;
    for (int kt = 0; kt < numKT; kt++) {
        const int ch0 = kt * 8;
        if (FIRST) {
            const int ch = tid & 7;
            const int rb = tid >> 3;
#pragma unroll
            for (int p = 0; p < 4; p++) {
                int row = rb + p * 32;
                float p0 = 0.f, p1 = 0.f, p2 = 0.f, p3 = 0.f;
                if (ch0 + ch < C_in) {
                    int m = m0 + row;
                    float v = in[(m >> 10) * (2 * NPTS) + (ch0 + ch) * NPTS + (m & (NPTS - 1))];
                    float t = fast_tanh(v);
                    jacobi4(t, p0, p1, p2, p3);
                }
                int k = ch * 4;
                As[k + 0][row] = p0; As[k + 1][row] = p1;
                As[k + 2][row] = p2; As[k + 3][row] = p3;
            }
        } else {
            const int row = tid >> 1;
            const int chq = (tid & 1) * 4;
            const float4 v4 =
                *reinterpret_cast<const float4*>(&in[(size_t)(m0 + row) * C_in + ch0 + chq]);
            const float vv[4] = {v4.x, v4.y, v4.z, v4.w};
#pragma unroll
            for (int j = 0; j < 4; j++) {
                int cc = ch0 + chq + j;
                float t = fast_tanh((vv[j] - mean[cc]) * rstd[cc]);
                float p0, p1, p2, p3;
                jacobi4(t, p0, p1, p2, p3);
                int k = (chq + j) * 4;
                As[k + 0][row] = p0; As[k + 1][row] = p1;
                As[k + 2][row] = p2; As[k + 3][row] = p3;
            }
        }
#pragma unroll
        for (int p = 0; p < 2; p++) {
            int f = tid + p * 256;
            int ch = f >> 6;
            int o = f & 63;
            int cc = ch0 + ch;
            int col = n0 + o;
            float4 wv = make_float4(0.f, 0.f, 0.f, 0.f);
            if (cc < C_in && col < C_out)
                wv = *reinterpret_cast<const float4*>(&w[((size_t)cc * C_out + col) * 4]);
            int k = ch * 4;
            Bs[k + 0][o] = wv.x; Bs[k + 1][o] = wv.y;
            Bs[k + 2][o] = wv.z; Bs[k + 3][o] = wv.w;
        }
        __syncthreads();

#pragma unroll
        for (int k = 0; k < 32; k++) {
            float a[8], bv[4];
#pragma unroll
            for (int r = 0; r < 8; r++) a[r] = As[k][trow * 8 + r];
#pragma unroll
            for (int c = 0; c < 4; c++) bv[c] = Bs[k][tcol * 4 + c];
#pragma unroll
            for (int r = 0; r < 8; r++)
#pragma unroll
                for (int c = 0; c < 4; c++) acc[r][c] = fmaf(a[r], bv[c], acc[r][c]);
        }
        __syncthreads();
    }

    if (LAST) {
#pragma unroll
        for (int r = 0; r < 8; r++) {
            int m = m0 + trow * 8 + r;
            int bb = m >> 10, n = m & (NPTS - 1);
#pragma unroll
            for (int c = 0; c < 4; c++) {
                int col = n0 + tcol * 4 + c;
                if (col < C_out) out[((size_t)bb * C_out + col) * NPTS + n] = acc[r][c];
            }
        }
    } else {
#pragma unroll
        for (int r = 0; r < 8; r++) {
            size_t m = m0 + trow * 8 + r;
            float4 v = make_float4(acc[r][0], acc[r][1], acc[r][2], acc[r][3]);
            *reinterpret_cast<float4*>(&out[m * C_out + n0 + tcol * 4]) = v;
        }
        float s[4] = {0, 0, 0, 0}, q[4] = {0, 0, 0, 0};
#pragma unroll
        for (int r = 0; r < 8; r++)
#pragma unroll
            for (int c = 0; c < 4; c++) {
                s[c] += acc[r][c];
                q[c] += acc[r][c] * acc[r][c];
            }
#pragma unroll
        for (int c = 0; c < 4; c++) {
            redS[trow][tcol * 4 + c] = s[c];
            redQ[trow][tcol * 4 + c] = q[c];
        }
        __syncthreads();
        if (tid < 64 && (n0 + tid) < C_out) {
            float ts = 0.f, tq = 0.f;
#pragma unroll
            for (int r = 0; r < 16; r++) { ts += redS[r][tid]; tq += redQ[r][tid]; }
            atomicAdd(&ssum[n0 + tid], ts);
            atomicAdd(&ssq[n0 + tid], tq);
        }
    }
}

// ---------------- launch ----------------
static inline int cdiv(int a, int b) { return (a + b - 1) / b; }

extern "C" void kernel_launch(void* const* d_in, const int* in_sizes, int n_in,
                              void* d_out, int out_size) {
    (void)in_sizes; (void)n_in; (void)out_size;
    const float* x   = (const float*)d_in[0];
    const float* w1  = (const float*)d_in[1];
    const float* w2  = (const float*)d_in[2];
    const float* w3  = (const float*)d_in[3];
    const float* w4  = (const float*)d_in[4];
    const float* w5  = (const float*)d_in[5];
    const float* w6  = (const float*)d_in[6];
    const float* w7  = (const float*)d_in[7];
    const float* w8  = (const float*)d_in[8];
    const float* w9  = (const float*)d_in[9];
    const float* w10 = (const float*)d_in[10];
    float* outp = (float*)d_out;

    float *z1, *z2, *z3, *z4, *z6, *z7, *z8, *z9;
    float *sum, *sq, *mean, *rstd, *cst6;
    cudaGetSymbolAddress((void**)&z1, g_z1);
    cudaGetSymbolAddress((void**)&z2, g_z2);
    cudaGetSymbolAddress((void**)&z3, g_z3);
    cudaGetSymbolAddress((void**)&z4, g_z4);
    cudaGetSymbolAddress((void**)&z6, g_z6);
    cudaGetSymbolAddress((void**)&z7, g_z7);
    cudaGetSymbolAddress((void**)&z8, g_z8);
    cudaGetSymbolAddress((void**)&z9, g_z9);
    cudaGetSymbolAddress((void**)&sum, g_sum);
    cudaGetSymbolAddress((void**)&sq, g_sq);
    cudaGetSymbolAddress((void**)&mean, g_mean);
    cudaGetSymbolAddress((void**)&rstd, g_rstd);
    cudaGetSymbolAddress((void**)&cst6, g_const6);

    cudaFuncSetAttribute(kan_mma<false, false>, cudaFuncAttributeMaxDynamicSharedMemorySize, SMEM_MMA);
    cudaFuncSetAttribute(kan_mma<true, false>,  cudaFuncAttributeMaxDynamicSharedMemorySize, SMEM_MMA);
    cudaFuncSetAttribute(kan_mma<false, true>,  cudaFuncAttributeMaxDynamicSharedMemorySize, SMEM_MMA);

    zero_kernel<<<cdiv(BATCH * 1024, 256), 256>>>();

    // L1: x(2) -> z1(64)   [scalar FIRST]
    kan_gemm<true, false><<<dim3(1, 256), 256>>>(
        x, w1, nullptr, nullptr, z1, sum + 0, sq + 0, 2, 64);
    finalize_kernel<<<1, 64>>>(sum + 0, sq + 0, mean + 0, rstd + 0, 64);

    // L2: z1(64) -> z2(64)   [scalar]
    kan_gemm<false, false><<<dim3(1, 256), 256>>>(
        z1, w2, mean + 0, rstd + 0, z2, sum + 64, sq + 64, 64, 64);
    finalize_kernel<<<1, 64>>>(sum + 64, sq + 64, mean + 64, rstd + 64, 64);

    // L3: z2(64) -> z3(64)   [scalar]
    kan_gemm<false, false><<<dim3(1, 256), 256>>>(
        z2, w3, mean + 64, rstd + 64, z3, sum + 128, sq + 128, 64, 64);
    finalize_kernel<<<1, 64>>>(sum + 128, sq + 128, mean + 128, rstd + 128, 64);

    // L4: z3(64) -> z4(128)   [HMMA]
    kan_mma<false, false><<<dim3(1, 256), 256, SMEM_MMA>>>(
        z3, w4, mean + 128, rstd + 128, z4, sum + 192, sq + 192, nullptr, 64, 128);
    finalize_kernel<<<2, 64>>>(sum + 192, sq + 192, mean + 192, rstd + 192, 128);

    // L5: z4(128) -> (maxpool + stats only, z5 never stored)   [HMMA, MAXPOOL]
    kan_mma<true, false><<<dim3(8, 256), 256, SMEM_MMA>>>(
        z4, w5, mean + 192, rstd + 192, nullptr, sum + 320, sq + 320, nullptr, 128, 1024);
    finalize_kernel<<<16, 64>>>(sum + 320, sq + 320, mean + 320, rstd + 320, 1024);

    // gf constant contribution to layer 6
    const6_kernel<<<dim3(8, 8), 64>>>(w6);

    // L6: local z2(64) -> z6(512), + const6   [HMMA, HASCONST]
    kan_mma<false, true><<<dim3(4, 256), 256, SMEM_MMA>>>(
        z2, w6, mean + 64, rstd + 64, z6, sum + 1344, sq + 1344, cst6, 64, 512);
    finalize_kernel<<<8, 64>>>(sum + 1344, sq + 1344, mean + 1344, rstd + 1344, 512);

    // L7: z6(512) -> z7(256)   [HMMA]
    kan_mma<false, false><<<dim3(2, 256), 256, SMEM_MMA>>>(
        z6, w7, mean + 1344, rstd + 1344, z7, sum + 1856, sq + 1856, nullptr, 512, 256);
    finalize_kernel<<<4, 64>>>(sum + 1856, sq + 1856, mean + 1856, rstd + 1856, 256);

    // L8: z7(256) -> z8(128)   [HMMA]
    kan_mma<false, false><<<dim3(1, 256), 256, SMEM_MMA>>>(
        z7, w8, mean + 1856, rstd + 1856, z8, sum + 2112, sq + 2112, nullptr, 256, 128);
    finalize_kernel<<<2, 64>>>(sum + 2112, sq + 2112, mean + 2112, rstd + 2112, 128);

    // L9: z8(128) -> z9(128)   [HMMA]
    kan_mma<false, false><<<dim3(1, 256), 256, SMEM_MMA>>>(
        z8, w9, mean + 2112, rstd + 2112, z9, sum + 2240, sq + 2240, nullptr, 128, 128);
    finalize_kernel<<<2, 64>>>(sum + 2240, sq + 2240, mean + 2240, rstd + 2240, 128);

    // L10: z9(128) -> out (B, 3, N), no BN   [scalar LAST]
    kan_gemm<false, true><<<dim3(1, 256), 256>>>(
        z9, w10, mean + 2240, rstd + 2240, outp, nullptr, nullptr, 128, 3);
}